// round 10
// baseline (speedup 1.0000x reference)
#include <cuda_runtime.h>
#include <math.h>
#include <stdint.h>

#define OBS 17
#define ACT 4
#define HID 64
#define LOG_2PI 1.8378770664093453f
#define TPB 256
#define ROWS 64
typedef unsigned long long ull;

// ---- shared memory layout (float offsets) ----
#define F_W1   0        // [17][128]  W1 combined, k-major
#define F_X    2176     // [17][64]   X^T
#define F_H    3264     // [128][64]  h1 (j 0-63 actor, 64-127 critic)
#define F_W2   11456    // [64][128]  W2 combined, k-major
#define F_P    19648    // [64][8]    per-row results m0..m3, value
#define F_B1   20160    // 128
#define F_B2   20288    // 128
#define F_W3A  20416    // 64 float4
#define F_W3C  20672    // 64
#define F_QINV 20736    // 16
#define F_MISC 20752    // cb3, s0, entropy
#define F_LOG  20756
#define F_INV  20760
#define SMEM_FLOATS 20764
#define SMEM_BYTES (SMEM_FLOATS * 4)

__device__ float g_Qinv[16];

__device__ __forceinline__ float tanh_fast(float v) {
    float r; asm("tanh.approx.f32 %0, %1;" : "=f"(r) : "f"(v)); return r;
}
__device__ __forceinline__ ull fma2(ull a, ull b, ull c) {
    ull d; asm("fma.rn.f32x2 %0, %1, %2, %3;" : "=l"(d) : "l"(a), "l"(b), "l"(c)); return d;
}
__device__ __forceinline__ ull dup2(float v) {
    ull d; asm("mov.b64 %0, {%1, %1};" : "=l"(d) : "f"(v)); return d;
}
__device__ __forceinline__ float2 upk(ull p) {
    float2 r; asm("mov.b64 {%0, %1}, %2;" : "=f"(r.x), "=f"(r.y) : "l"(p)); return r;
}

// ---------------------------------------------------------------------------
// Prep: Qinv = (tril(L) tril(L)^T + 1e-4 I)^{-1}, once, in double.
// ---------------------------------------------------------------------------
__global__ void qinv_kernel(const float* __restrict__ L) {
    if (threadIdx.x != 0 || blockIdx.x != 0) return;
    double Lt[4][4];
    for (int i = 0; i < 4; i++)
        for (int j = 0; j < 4; j++)
            Lt[i][j] = (j <= i) ? (double)L[i * 4 + j] : 0.0;
    double M[4][8];
    for (int i = 0; i < 4; i++) {
        for (int j = 0; j < 4; j++) {
            double s = (i == j) ? 1e-4 : 0.0;
            for (int k = 0; k < 4; k++) s += Lt[i][k] * Lt[j][k];
            M[i][j] = s;
            M[i][4 + j] = (i == j) ? 1.0 : 0.0;
        }
    }
    for (int c = 0; c < 4; c++) {
        int p = c;
        for (int r = c + 1; r < 4; r++) if (fabs(M[r][c]) > fabs(M[p][c])) p = r;
        if (p != c) for (int j = 0; j < 8; j++) { double t = M[c][j]; M[c][j] = M[p][j]; M[p][j] = t; }
        double inv = 1.0 / M[c][c];
        for (int j = 0; j < 8; j++) M[c][j] *= inv;
        for (int r = 0; r < 4; r++) if (r != c) {
            double f = M[r][c];
            for (int j = 0; j < 8; j++) M[r][j] -= f * M[c][j];
        }
    }
    for (int i = 0; i < 4; i++)
        for (int j = 0; j < 4; j++)
            g_Qinv[i * 4 + j] = (float)M[i][4 + j];
}

// ---------------------------------------------------------------------------
// Main kernel: block-GEMM, 64 rows/block, 256 threads.
// ---------------------------------------------------------------------------
__global__ __launch_bounds__(TPB, 2) void fused_kernel(
    const float* __restrict__ x, const float* __restrict__ sdfs,
    const float* __restrict__ grads, const float* __restrict__ f_x,
    const float* __restrict__ g_x, const float* __restrict__ action,
    const float* __restrict__ cW1, const float* __restrict__ cb1,
    const float* __restrict__ cW2, const float* __restrict__ cb2,
    const float* __restrict__ cW3, const float* __restrict__ cb3,
    const float* __restrict__ aW1, const float* __restrict__ ab1,
    const float* __restrict__ aW2, const float* __restrict__ ab2,
    const float* __restrict__ aW3, const float* __restrict__ ab3,
    const float* __restrict__ logstd, const float* __restrict__ s0,
    float* __restrict__ out, int N)
{
    extern __shared__ __align__(16) float sm[];
    const int tid = threadIdx.x;

    // ================= staging =================
    for (int i = tid; i < 17 * 128; i += TPB) {
        const int k = i >> 7, o = i & 127;
        sm[F_W1 + i] = (o < 64) ? aW1[k * 64 + o] : cW1[k * 64 + (o - 64)];
    }
    for (int i = tid; i < 64 * 128; i += TPB) {
        const int k = i >> 7, o = i & 127;
        sm[F_W2 + i] = (o < 64) ? aW2[k * 64 + o] : cW2[k * 64 + (o - 64)];
    }
    if (tid < ROWS) {
        const int rowG = blockIdx.x * ROWS + tid;
        const bool ok = rowG < N;
        const int rl = ok ? rowG : 0;
#pragma unroll
        for (int k = 0; k < OBS; k++)
            sm[F_X + k * 64 + tid] = ok ? x[rl * OBS + k] : 0.0f;
    }
    if (tid < 64) {
        sm[F_B1 + tid] = ab1[tid]; sm[F_B1 + 64 + tid] = cb1[tid];
        sm[F_B2 + tid] = ab2[tid]; sm[F_B2 + 64 + tid] = cb2[tid];
        ((float4*)&sm[F_W3A])[tid] = ((const float4*)aW3)[tid];
        sm[F_W3C + tid] = cW3[tid];
    }
    if (tid < 16) sm[F_QINV + tid] = g_Qinv[tid];
    if (tid < 4) { const float ls = logstd[tid]; sm[F_LOG + tid] = ls; sm[F_INV + tid] = expf(-ls); }
    if (tid == 0) {
        sm[F_MISC + 0] = cb3[0]; sm[F_MISC + 1] = s0[0];
        float e = 0.0f;
        for (int a = 0; a < ACT; a++) e += 0.5f + 0.5f * LOG_2PI + logstd[a];
        sm[F_MISC + 2] = e;
    }
    __syncthreads();

    // ================= phase 1: C1[64r x 128o] = X @ W1comb =================
    {
        const int og = tid & 15;       // 16 groups x 8 outs
        const int rg = tid >> 4;       // 16 groups x 4 rows
        ull acc[16];
#pragma unroll
        for (int p = 0; p < 16; p++) acc[p] = 0ull;
#pragma unroll
        for (int k = 0; k < OBS; k++) {
            const float4 av = *(const float4*)&sm[F_X + k * 64 + rg * 4];
            const ulonglong2 b0 = *(const ulonglong2*)&sm[F_W1 + k * 128 + og * 8];
            const ulonglong2 b1 = *(const ulonglong2*)&sm[F_W1 + k * 128 + og * 8 + 4];
            const ull a0 = dup2(av.x), a1 = dup2(av.y), a2 = dup2(av.z), a3 = dup2(av.w);
            acc[0]  = fma2(b0.x, a0, acc[0]);  acc[1]  = fma2(b0.y, a0, acc[1]);
            acc[2]  = fma2(b1.x, a0, acc[2]);  acc[3]  = fma2(b1.y, a0, acc[3]);
            acc[4]  = fma2(b0.x, a1, acc[4]);  acc[5]  = fma2(b0.y, a1, acc[5]);
            acc[6]  = fma2(b1.x, a1, acc[6]);  acc[7]  = fma2(b1.y, a1, acc[7]);
            acc[8]  = fma2(b0.x, a2, acc[8]);  acc[9]  = fma2(b0.y, a2, acc[9]);
            acc[10] = fma2(b1.x, a2, acc[10]); acc[11] = fma2(b1.y, a2, acc[11]);
            acc[12] = fma2(b0.x, a3, acc[12]); acc[13] = fma2(b0.y, a3, acc[13]);
            acc[14] = fma2(b1.x, a3, acc[14]); acc[15] = fma2(b1.y, a3, acc[15]);
        }
        // bias + tanh, store transposed into sH[j][r]
        float col[8][4];
#pragma unroll
        for (int r = 0; r < 4; r++)
#pragma unroll
            for (int p = 0; p < 4; p++) {
                const float2 t = upk(acc[r * 4 + p]);
                col[2 * p][r]     = tanh_fast(t.x + sm[F_B1 + og * 8 + 2 * p]);
                col[2 * p + 1][r] = tanh_fast(t.y + sm[F_B1 + og * 8 + 2 * p + 1]);
            }
#pragma unroll
        for (int o = 0; o < 8; o++)
            *(float4*)&sm[F_H + (og * 8 + o) * 64 + rg * 4] =
                make_float4(col[o][0], col[o][1], col[o][2], col[o][3]);
    }
    __syncthreads();

    // ================= phase 2: per-net C2[64 x 64] + fused L3 =================
    {
        const int half = tid >> 7;     // 0 actor, 1 critic
        const int t7 = tid & 127;
        const int og = t7 & 7;         // 8 groups x 8 outs
        const int rg = t7 >> 3;        // 16 groups x 4 rows
        const int hBase = F_H + half * 64 * 64;
        const int wBase = F_W2 + half * 64;
        ull acc[16];
#pragma unroll
        for (int p = 0; p < 16; p++) acc[p] = 0ull;
#pragma unroll 8
        for (int k = 0; k < HID; k++) {
            const float4 av = *(const float4*)&sm[hBase + k * 64 + rg * 4];
            const ulonglong2 b0 = *(const ulonglong2*)&sm[wBase + k * 128 + og * 8];
            const ulonglong2 b1 = *(const ulonglong2*)&sm[wBase + k * 128 + og * 8 + 4];
            const ull a0 = dup2(av.x), a1 = dup2(av.y), a2 = dup2(av.z), a3 = dup2(av.w);
            acc[0]  = fma2(b0.x, a0, acc[0]);  acc[1]  = fma2(b0.y, a0, acc[1]);
            acc[2]  = fma2(b1.x, a0, acc[2]);  acc[3]  = fma2(b1.y, a0, acc[3]);
            acc[4]  = fma2(b0.x, a1, acc[4]);  acc[5]  = fma2(b0.y, a1, acc[5]);
            acc[6]  = fma2(b1.x, a1, acc[6]);  acc[7]  = fma2(b1.y, a1, acc[7]);
            acc[8]  = fma2(b0.x, a2, acc[8]);  acc[9]  = fma2(b0.y, a2, acc[9]);
            acc[10] = fma2(b1.x, a2, acc[10]); acc[11] = fma2(b1.y, a2, acc[11]);
            acc[12] = fma2(b0.x, a3, acc[12]); acc[13] = fma2(b0.y, a3, acc[13]);
            acc[14] = fma2(b1.x, a3, acc[14]); acc[15] = fma2(b1.y, a3, acc[15]);
        }
        // tanh + L3 partials; deterministic shfl-reduce over og lanes (lane&7)
        if (half == 0) {
            float pm[4][4];
#pragma unroll
            for (int r = 0; r < 4; r++) { pm[r][0] = pm[r][1] = pm[r][2] = pm[r][3] = 0.0f; }
#pragma unroll
            for (int r = 0; r < 4; r++)
#pragma unroll
                for (int p = 0; p < 4; p++) {
                    const float2 t = upk(acc[r * 4 + p]);
                    const float h0 = tanh_fast(t.x + sm[F_B2 + og * 8 + 2 * p]);
                    const float h1 = tanh_fast(t.y + sm[F_B2 + og * 8 + 2 * p + 1]);
                    const float4 w0 = ((const float4*)&sm[F_W3A])[og * 8 + 2 * p];
                    const float4 w1 = ((const float4*)&sm[F_W3A])[og * 8 + 2 * p + 1];
                    pm[r][0] += h0 * w0.x + h1 * w1.x;
                    pm[r][1] += h0 * w0.y + h1 * w1.y;
                    pm[r][2] += h0 * w0.z + h1 * w1.z;
                    pm[r][3] += h0 * w0.w + h1 * w1.w;
                }
#pragma unroll
            for (int r = 0; r < 4; r++)
#pragma unroll
                for (int c = 0; c < 4; c++) {
                    pm[r][c] += __shfl_xor_sync(0xffffffffu, pm[r][c], 1);
                    pm[r][c] += __shfl_xor_sync(0xffffffffu, pm[r][c], 2);
                    pm[r][c] += __shfl_xor_sync(0xffffffffu, pm[r][c], 4);
                }
            if (og == 0) {
#pragma unroll
                for (int r = 0; r < 4; r++) {
                    const int row = rg * 4 + r;
                    sm[F_P + row * 8 + 0] = pm[r][0] + ab3[0];
                    sm[F_P + row * 8 + 1] = pm[r][1] + ab3[1];
                    sm[F_P + row * 8 + 2] = pm[r][2] + ab3[2];
                    sm[F_P + row * 8 + 3] = pm[r][3] + ab3[3];
                }
            }
        } else {
            float pv[4] = {0.f, 0.f, 0.f, 0.f};
#pragma unroll
            for (int r = 0; r < 4; r++)
#pragma unroll
                for (int p = 0; p < 4; p++) {
                    const float2 t = upk(acc[r * 4 + p]);
                    pv[r] += tanh_fast(t.x + sm[F_B2 + 64 + og * 8 + 2 * p]) * sm[F_W3C + og * 8 + 2 * p];
                    pv[r] += tanh_fast(t.y + sm[F_B2 + 64 + og * 8 + 2 * p + 1]) * sm[F_W3C + og * 8 + 2 * p + 1];
                }
#pragma unroll
            for (int r = 0; r < 4; r++) {
                pv[r] += __shfl_xor_sync(0xffffffffu, pv[r], 1);
                pv[r] += __shfl_xor_sync(0xffffffffu, pv[r], 2);
                pv[r] += __shfl_xor_sync(0xffffffffu, pv[r], 4);
            }
            if (og == 0) {
#pragma unroll
                for (int r = 0; r < 4; r++)
                    sm[F_P + (rg * 4 + r) * 8 + 4] = pv[r] + sm[F_MISC + 0];
            }
        }
    }
    __syncthreads();

    // ================= phase 3: QP + outputs (one thread per row) =================
    if (tid < ROWS) {
        const int rowG = blockIdx.x * ROWS + tid;
        const bool ok = rowG < N;
        const int rl = ok ? rowG : 0;
        const float m0 = sm[F_P + tid * 8 + 0];
        const float m1 = sm[F_P + tid * 8 + 1];
        const float m2 = sm[F_P + tid * 8 + 2];
        const float m3 = sm[F_P + tid * 8 + 3];
        const float value = sm[F_P + tid * 8 + 4];

        float G0 = 0.f, G1 = 0.f, G2 = 0.f, G3 = 0.f, gf = 0.f;
#pragma unroll
        for (int s = 0; s < OBS; s++) {
            const float gr = grads[rl * OBS + s];
            const float4 gx = *(const float4*)&g_x[rl * OBS * ACT + s * ACT];
            G0 -= gr * gx.x; G1 -= gr * gx.y; G2 -= gr * gx.z; G3 -= gr * gx.w;
            gf += gr * f_x[rl * OBS + s];
        }
        const float4 av = *(const float4*)&action[rl * ACT];
        const float h = sm[F_MISC + 1] + sdfs[rl] + gf
                      - (G0 * av.x + G1 * av.y + G2 * av.z + G3 * av.w);
        const float* q = &sm[F_QINV];
        const float v0 = q[0]  * G0 + q[1]  * G1 + q[2]  * G2 + q[3]  * G3;
        const float v1 = q[4]  * G0 + q[5]  * G1 + q[6]  * G2 + q[7]  * G3;
        const float v2 = q[8]  * G0 + q[9]  * G1 + q[10] * G2 + q[11] * G3;
        const float v3 = q[12] * G0 + q[13] * G1 + q[14] * G2 + q[15] * G3;
        const float denom = G0 * v0 + G1 * v1 + G2 * v2 + G3 * v3;
        const float lam = fmaxf(0.0f, -h / denom);

        const float z0 = (av.x - m0) * sm[F_INV + 0];
        const float z1 = (av.y - m1) * sm[F_INV + 1];
        const float z2 = (av.z - m2) * sm[F_INV + 2];
        const float z3 = (av.w - m3) * sm[F_INV + 3];
        const float lp = -0.5f * (z0 * z0 + z1 * z1 + z2 * z2 + z3 * z3)
                       - (sm[F_LOG + 0] + sm[F_LOG + 1] + sm[F_LOG + 2] + sm[F_LOG + 3])
                       - 2.0f * LOG_2PI;

        if (ok) {
            *(float4*)&out[rowG * 4] = make_float4(m0 - lam * v0, m1 - lam * v1,
                                                  m2 - lam * v2, m3 - lam * v3);
            out[4 * N + rowG] = lp;
            out[5 * N + rowG] = sm[F_MISC + 2];
            out[6 * N + rowG] = value;
        }
    }
}

extern "C" void kernel_launch(void* const* d_in, const int* in_sizes, int n_in,
                              void* d_out, int out_size) {
    const float* x      = (const float*)d_in[0];
    const float* sdfs   = (const float*)d_in[1];
    const float* grads  = (const float*)d_in[2];
    const float* f_x    = (const float*)d_in[3];
    const float* g_x    = (const float*)d_in[4];
    const float* action = (const float*)d_in[5];
    const float* cW1 = (const float*)d_in[6];
    const float* cb1 = (const float*)d_in[7];
    const float* cW2 = (const float*)d_in[8];
    const float* cb2 = (const float*)d_in[9];
    const float* cW3 = (const float*)d_in[10];
    const float* cb3 = (const float*)d_in[11];
    const float* aW1 = (const float*)d_in[12];
    const float* ab1 = (const float*)d_in[13];
    const float* aW2 = (const float*)d_in[14];
    const float* ab2 = (const float*)d_in[15];
    const float* aW3 = (const float*)d_in[16];
    const float* ab3 = (const float*)d_in[17];
    const float* logstd = (const float*)d_in[18];
    const float* L      = (const float*)d_in[19];
    const float* s0     = (const float*)d_in[20];

    const int N = in_sizes[0] / OBS;
    float* out = (float*)d_out;

    cudaFuncSetAttribute(fused_kernel,
                         cudaFuncAttributeMaxDynamicSharedMemorySize, SMEM_BYTES);

    qinv_kernel<<<1, 32>>>(L);
    const int blocks = (N + ROWS - 1) / ROWS;
    fused_kernel<<<blocks, TPB, SMEM_BYTES>>>(x, sdfs, grads, f_x, g_x, action,
                                              cW1, cb1, cW2, cb2, cW3, cb3,
                                              aW1, ab1, aW2, ab2, aW3, ab3,
                                              logstd, s0, out, N);
}

// round 11
// speedup vs baseline: 1.5431x; 1.5431x over previous
#include <cuda_runtime.h>
#include <cuda_fp16.h>
#include <math.h>

#define OBS 17
#define ACT 4
#define HID 64
#define LOG_2PI 1.8378770664093453f
#define TPB 128
typedef unsigned long long ull;

__device__ float g_Qinv[16];

__device__ __forceinline__ float tanh_fast(float v) {
    float r; asm("tanh.approx.f32 %0, %1;" : "=f"(r) : "f"(v)); return r;
}
__device__ __forceinline__ ull fma2(ull a, ull b, ull c) {
    ull d; asm("fma.rn.f32x2 %0, %1, %2, %3;" : "=l"(d) : "l"(a), "l"(b), "l"(c)); return d;
}
__device__ __forceinline__ ull dup2(float v) {
    ull d; asm("mov.b64 %0, {%1, %1};" : "=l"(d) : "f"(v)); return d;
}
__device__ __forceinline__ ull pk2(float x, float y) {
    ull d; asm("mov.b64 %0, {%1, %2};" : "=l"(d) : "f"(x), "f"(y)); return d;
}
__device__ __forceinline__ float2 upk(ull p) {
    float2 r; asm("mov.b64 {%0, %1}, %2;" : "=f"(r.x), "=f"(r.y) : "l"(p)); return r;
}

// ---------------------------------------------------------------------------
// Prep: Qinv = (tril(L) tril(L)^T + 1e-4 I)^{-1}, once, in double.
// ---------------------------------------------------------------------------
__global__ void qinv_kernel(const float* __restrict__ L) {
    if (threadIdx.x != 0 || blockIdx.x != 0) return;
    double Lt[4][4];
    for (int i = 0; i < 4; i++)
        for (int j = 0; j < 4; j++)
            Lt[i][j] = (j <= i) ? (double)L[i * 4 + j] : 0.0;
    double M[4][8];
    for (int i = 0; i < 4; i++) {
        for (int j = 0; j < 4; j++) {
            double s = (i == j) ? 1e-4 : 0.0;
            for (int k = 0; k < 4; k++) s += Lt[i][k] * Lt[j][k];
            M[i][j] = s;
            M[i][4 + j] = (i == j) ? 1.0 : 0.0;
        }
    }
    for (int c = 0; c < 4; c++) {
        int p = c;
        for (int r = c + 1; r < 4; r++) if (fabs(M[r][c]) > fabs(M[p][c])) p = r;
        if (p != c) for (int j = 0; j < 8; j++) { double t = M[c][j]; M[c][j] = M[p][j]; M[p][j] = t; }
        double inv = 1.0 / M[c][c];
        for (int j = 0; j < 8; j++) M[c][j] *= inv;
        for (int r = 0; r < 4; r++) if (r != c) {
            double f = M[r][c];
            for (int j = 0; j < 8; j++) M[r][j] -= f * M[c][j];
        }
    }
    for (int i = 0; i < 4; i++)
        for (int j = 0; j < 4; j++)
            g_Qinv[i * 4 + j] = (float)M[i][4 + j];
}

// ---------------------------------------------------------------------------
// QP + outputs for one row
// ---------------------------------------------------------------------------
__device__ __forceinline__ void epilogue_row(
    int row, int N, bool valid,
    const float* __restrict__ grads, const float* __restrict__ f_x,
    const float* __restrict__ g_x, const float* __restrict__ sdfs,
    const float* __restrict__ action,
    const float* sQinv, const float* sMisc, const float* sLogstd, const float* sInvStd,
    float m0, float m1, float m2, float m3, float value,
    float* __restrict__ out)
{
    const int rl = valid ? row : 0;
    float G0 = 0.f, G1 = 0.f, G2 = 0.f, G3 = 0.f, gf = 0.f;
#pragma unroll
    for (int s = 0; s < OBS; s++) {
        const float gr = grads[rl * OBS + s];
        const float4 gx = *(const float4*)&g_x[rl * OBS * ACT + s * ACT];
        G0 -= gr * gx.x; G1 -= gr * gx.y; G2 -= gr * gx.z; G3 -= gr * gx.w;
        gf += gr * f_x[rl * OBS + s];
    }
    const float4 av = *(const float4*)&action[rl * ACT];
    const float h = sMisc[1] + sdfs[rl] + gf
                  - (G0 * av.x + G1 * av.y + G2 * av.z + G3 * av.w);
    const float v0 = sQinv[0]  * G0 + sQinv[1]  * G1 + sQinv[2]  * G2 + sQinv[3]  * G3;
    const float v1 = sQinv[4]  * G0 + sQinv[5]  * G1 + sQinv[6]  * G2 + sQinv[7]  * G3;
    const float v2 = sQinv[8]  * G0 + sQinv[9]  * G1 + sQinv[10] * G2 + sQinv[11] * G3;
    const float v3 = sQinv[12] * G0 + sQinv[13] * G1 + sQinv[14] * G2 + sQinv[15] * G3;
    const float denom = G0 * v0 + G1 * v1 + G2 * v2 + G3 * v3;
    const float lam = fmaxf(0.0f, -h / denom);

    float z0 = (av.x - m0) * sInvStd[0];
    float z1 = (av.y - m1) * sInvStd[1];
    float z2 = (av.z - m2) * sInvStd[2];
    float z3 = (av.w - m3) * sInvStd[3];
    float lp = -0.5f * (z0 * z0 + z1 * z1 + z2 * z2 + z3 * z3)
               - (sLogstd[0] + sLogstd[1] + sLogstd[2] + sLogstd[3])
               - 2.0f * LOG_2PI;

    if (valid) {
        *(float4*)&out[row * 4] = make_float4(m0 - lam * v0, m1 - lam * v1,
                                              m2 - lam * v2, m3 - lam * v3);
        out[4 * N + row] = lp;
        out[5 * N + row] = sMisc[2];
        out[6 * N + row] = value;
    }
}

// ---------------------------------------------------------------------------
// Main fused kernel: 2 rows/thread, packed f32x2 math, h1 stored as half2
// (halves the activation register footprint -> 3 blocks/SM).
// ---------------------------------------------------------------------------
__global__ __launch_bounds__(TPB, 3) void fused_kernel(
    const float* __restrict__ x, const float* __restrict__ sdfs,
    const float* __restrict__ grads, const float* __restrict__ f_x,
    const float* __restrict__ g_x, const float* __restrict__ action,
    const float* __restrict__ cW1, const float* __restrict__ cb1,
    const float* __restrict__ cW2, const float* __restrict__ cb2,
    const float* __restrict__ cW3, const float* __restrict__ cb3,
    const float* __restrict__ aW1, const float* __restrict__ ab1,
    const float* __restrict__ aW2, const float* __restrict__ ab2,
    const float* __restrict__ aW3, const float* __restrict__ ab3,
    const float* __restrict__ logstd, const float* __restrict__ s0,
    float* __restrict__ out, int N)
{
    __shared__ __align__(16) float sAW1[OBS * HID];
    __shared__ __align__(16) float sAW2[HID * HID];
    __shared__ __align__(16) float sAW3[HID * ACT];
    __shared__ __align__(16) float sCW1[OBS * HID];
    __shared__ __align__(16) float sCW2[HID * HID];
    __shared__ __align__(16) float sCW3[HID];
    __shared__ __align__(16) float sAb1[HID], sAb2[HID], sCb1[HID], sCb2[HID];
    __shared__ __align__(16) float sAb3[ACT], sLogstd[ACT], sInvStd[ACT];
    __shared__ __align__(16) float sQinv[16];
    __shared__ __align__(16) float sMisc[4]; // 0: cb3, 1: s0, 2: entropy

    const int tid = threadIdx.x;
    for (int i = tid; i < OBS * HID; i += TPB) { sAW1[i] = aW1[i]; sCW1[i] = cW1[i]; }
    for (int i = tid; i < HID * HID; i += TPB) { sAW2[i] = aW2[i]; sCW2[i] = cW2[i]; }
    for (int i = tid; i < HID * ACT; i += TPB) sAW3[i] = aW3[i];
    if (tid < HID) {
        sAb1[tid] = ab1[tid]; sAb2[tid] = ab2[tid];
        sCb1[tid] = cb1[tid]; sCb2[tid] = cb2[tid];
        sCW3[tid] = cW3[tid];
    }
    if (tid < ACT) {
        float ls = logstd[tid];
        sAb3[tid] = ab3[tid];
        sLogstd[tid] = ls;
        sInvStd[tid] = expf(-ls);
    }
    if (tid < 16) sQinv[tid] = g_Qinv[tid];
    if (tid == 0) {
        sMisc[0] = cb3[0];
        sMisc[1] = s0[0];
        float e = 0.0f;
        for (int a = 0; a < ACT; a++) e += 0.5f + 0.5f * LOG_2PI + logstd[a];
        sMisc[2] = e;
    }
    __syncthreads();

    const int r0 = blockIdx.x * (2 * TPB) + tid;
    const int r1 = r0 + TPB;
    const bool ok0 = r0 < N, ok1 = r1 < N;
    const int rl0 = ok0 ? r0 : 0;
    const int rl1 = ok1 ? r1 : 0;

    // ---- observations for both rows ----
    float xA[OBS], xB[OBS];
#pragma unroll
    for (int i = 0; i < OBS; i++) { xA[i] = x[rl0 * OBS + i]; xB[i] = x[rl1 * OBS + i]; }

    // h1 stored as packed half2: pair p holds h1[2p], h1[2p+1]  (32 regs/row)
    __half2 h1A[32], h1B[32];
    float mA0, mA1, mA2, mA3, mB0, mB1, mB2, mB3, valA, valB;

    // =============== ACTOR + CRITIC (net = 0/1) ===============
#pragma unroll 1
    for (int net = 0; net < 2; net++) {
        const float* W1 = net ? sCW1 : sAW1;
        const float* W2 = net ? sCW2 : sAW2;
        const float* B1 = net ? sCb1 : sAb1;
        const float* B2 = net ? sCb2 : sAb2;

        // ---- layer 1: two chunks of 32 outputs (16 ull accum per row per chunk) ----
#pragma unroll 1
        for (int c1 = 0; c1 < 2; c1++) {
            ull hA[16], hB[16];
            const ulonglong2* bp = (const ulonglong2*)&B1[c1 * 32];
#pragma unroll
            for (int q = 0; q < 8; q++) {
                ulonglong2 bb = bp[q];
                hA[2*q] = bb.x; hA[2*q+1] = bb.y;
                hB[2*q] = bb.x; hB[2*q+1] = bb.y;
            }
#pragma unroll 1
            for (int i = 0; i < OBS; i++) {
                const ull vA = dup2(xA[i]), vB = dup2(xB[i]);
                const ulonglong2* wp = (const ulonglong2*)&W1[i * HID + c1 * 32];
#pragma unroll
                for (int q = 0; q < 8; q++) {
                    ulonglong2 ww = wp[q];
                    hA[2*q]   = fma2(ww.x, vA, hA[2*q]);
                    hA[2*q+1] = fma2(ww.y, vA, hA[2*q+1]);
                    hB[2*q]   = fma2(ww.x, vB, hB[2*q]);
                    hB[2*q+1] = fma2(ww.y, vB, hB[2*q+1]);
                }
            }
#pragma unroll
            for (int p = 0; p < 16; p++) {
                float2 t = upk(hA[p]);
                h1A[c1 * 16 + p] = __floats2half2_rn(tanh_fast(t.x), tanh_fast(t.y));
                t = upk(hB[p]);
                h1B[c1 * 16 + p] = __floats2half2_rn(tanh_fast(t.x), tanh_fast(t.y));
            }
        }

        // ---- layer 2 (4 chunks of 16 outputs) + fused layer 3 ----
        ull mA01, mA23, mB01, mB23;   // actor mean pairs
        ull vpA, vpB;                 // critic value pairs
        if (net == 0) {
            mA01 = pk2(sAb3[0], sAb3[1]); mA23 = pk2(sAb3[2], sAb3[3]);
            mB01 = mA01; mB23 = mA23;
        } else {
            vpA = pk2(sMisc[0], 0.0f); vpB = vpA;
        }
#pragma unroll 1
        for (int c = 0; c < 4; c++) {
            ull aA[8], aB[8];
            const ulonglong2* bp = (const ulonglong2*)&B2[c * 16];
#pragma unroll
            for (int q = 0; q < 4; q++) {
                ulonglong2 bb = bp[q];
                aA[2*q] = bb.x; aA[2*q+1] = bb.y;
                aB[2*q] = bb.x; aB[2*q+1] = bb.y;
            }
            // ii indexes half2 pairs: k = 2*ii, 2*ii+1
#pragma unroll 4
            for (int ii = 0; ii < 32; ii++) {
                const float2 fA = __half22float2(h1A[ii]);
                const float2 fB = __half22float2(h1B[ii]);
                const ull a0 = dup2(fA.x), a1 = dup2(fA.y);
                const ull b0 = dup2(fB.x), b1 = dup2(fB.y);
                const ulonglong2* wp0 = (const ulonglong2*)&W2[(2*ii) * HID + c * 16];
                const ulonglong2* wp1 = (const ulonglong2*)&W2[(2*ii + 1) * HID + c * 16];
#pragma unroll
                for (int q = 0; q < 4; q++) {
                    ulonglong2 w0 = wp0[q];
                    aA[2*q]   = fma2(w0.x, a0, aA[2*q]);
                    aA[2*q+1] = fma2(w0.y, a0, aA[2*q+1]);
                    aB[2*q]   = fma2(w0.x, b0, aB[2*q]);
                    aB[2*q+1] = fma2(w0.y, b0, aB[2*q+1]);
                }
#pragma unroll
                for (int q = 0; q < 4; q++) {
                    ulonglong2 w1 = wp1[q];
                    aA[2*q]   = fma2(w1.x, a1, aA[2*q]);
                    aA[2*q+1] = fma2(w1.y, a1, aA[2*q+1]);
                    aB[2*q]   = fma2(w1.x, b1, aB[2*q]);
                    aB[2*q+1] = fma2(w1.y, b1, aB[2*q+1]);
                }
            }
#pragma unroll
            for (int p = 0; p < 8; p++) {
                const int j = c * 16 + 2 * p;
                float2 tA = upk(aA[p]);
                tA.x = tanh_fast(tA.x); tA.y = tanh_fast(tA.y);
                float2 tB = upk(aB[p]);
                tB.x = tanh_fast(tB.x); tB.y = tanh_fast(tB.y);
                if (net == 0) {
                    const ulonglong2 w0 = *(const ulonglong2*)&sAW3[j * ACT];
                    const ulonglong2 w1 = *(const ulonglong2*)&sAW3[(j + 1) * ACT];
                    ull d;
                    d = dup2(tA.x); mA01 = fma2(w0.x, d, mA01); mA23 = fma2(w0.y, d, mA23);
                    d = dup2(tA.y); mA01 = fma2(w1.x, d, mA01); mA23 = fma2(w1.y, d, mA23);
                    d = dup2(tB.x); mB01 = fma2(w0.x, d, mB01); mB23 = fma2(w0.y, d, mB23);
                    d = dup2(tB.y); mB01 = fma2(w1.x, d, mB01); mB23 = fma2(w1.y, d, mB23);
                } else {
                    const ull wv = *(const ull*)&sCW3[j];
                    vpA = fma2(wv, pk2(tA.x, tA.y), vpA);
                    vpB = fma2(wv, pk2(tB.x, tB.y), vpB);
                }
            }
        }
        if (net == 0) {
            float2 a = upk(mA01), b = upk(mA23);
            mA0 = a.x; mA1 = a.y; mA2 = b.x; mA3 = b.y;
            a = upk(mB01); b = upk(mB23);
            mB0 = a.x; mB1 = a.y; mB2 = b.x; mB3 = b.y;
        } else {
            float2 a = upk(vpA); valA = a.x + a.y;
            a = upk(vpB); valB = a.x + a.y;
        }
    }

    // =============== QP + outputs, both rows ===============
    epilogue_row(r0, N, ok0, grads, f_x, g_x, sdfs, action,
                 sQinv, sMisc, sLogstd, sInvStd, mA0, mA1, mA2, mA3, valA, out);
    epilogue_row(r1, N, ok1, grads, f_x, g_x, sdfs, action,
                 sQinv, sMisc, sLogstd, sInvStd, mB0, mB1, mB2, mB3, valB, out);
}

extern "C" void kernel_launch(void* const* d_in, const int* in_sizes, int n_in,
                              void* d_out, int out_size) {
    const float* x      = (const float*)d_in[0];
    const float* sdfs   = (const float*)d_in[1];
    const float* grads  = (const float*)d_in[2];
    const float* f_x    = (const float*)d_in[3];
    const float* g_x    = (const float*)d_in[4];
    const float* action = (const float*)d_in[5];
    const float* cW1 = (const float*)d_in[6];
    const float* cb1 = (const float*)d_in[7];
    const float* cW2 = (const float*)d_in[8];
    const float* cb2 = (const float*)d_in[9];
    const float* cW3 = (const float*)d_in[10];
    const float* cb3 = (const float*)d_in[11];
    const float* aW1 = (const float*)d_in[12];
    const float* ab1 = (const float*)d_in[13];
    const float* aW2 = (const float*)d_in[14];
    const float* ab2 = (const float*)d_in[15];
    const float* aW3 = (const float*)d_in[16];
    const float* ab3 = (const float*)d_in[17];
    const float* logstd = (const float*)d_in[18];
    const float* L      = (const float*)d_in[19];
    const float* s0     = (const float*)d_in[20];

    const int N = in_sizes[0] / OBS;
    float* out = (float*)d_out;

    // 3 x 44KB static smem blocks need a >=132KB shared carveout.
    cudaFuncSetAttribute(fused_kernel,
                         cudaFuncAttributePreferredSharedMemoryCarveout, 100);

    qinv_kernel<<<1, 32>>>(L);
    const int rowsPerBlock = 2 * TPB;
    const int blocks = (N + rowsPerBlock - 1) / rowsPerBlock;
    fused_kernel<<<blocks, TPB>>>(x, sdfs, grads, f_x, g_x, action,
                                  cW1, cb1, cW2, cb2, cW3, cb3,
                                  aW1, ab1, aW2, ab2, aW3, ab3,
                                  logstd, s0, out, N);
}

// round 12
// speedup vs baseline: 1.6355x; 1.0599x over previous
#include <cuda_runtime.h>
#include <cuda_fp16.h>
#include <math.h>

#define OBS 17
#define ACT 4
#define HID 64
#define LOG_2PI 1.8378770664093453f
#define TPB 128
typedef unsigned long long ull;

__device__ float g_Qinv[16];

__device__ __forceinline__ float tanh_fast(float v) {
    float r; asm("tanh.approx.f32 %0, %1;" : "=f"(r) : "f"(v)); return r;
}
__device__ __forceinline__ ull fma2(ull a, ull b, ull c) {
    ull d; asm("fma.rn.f32x2 %0, %1, %2, %3;" : "=l"(d) : "l"(a), "l"(b), "l"(c)); return d;
}
__device__ __forceinline__ ull dup2(float v) {
    ull d; asm("mov.b64 %0, {%1, %1};" : "=l"(d) : "f"(v)); return d;
}
__device__ __forceinline__ ull pk2(float x, float y) {
    ull d; asm("mov.b64 %0, {%1, %2};" : "=l"(d) : "f"(x), "f"(y)); return d;
}
__device__ __forceinline__ float2 upk(ull p) {
    float2 r; asm("mov.b64 {%0, %1}, %2;" : "=f"(r.x), "=f"(r.y) : "l"(p)); return r;
}

// ---------------------------------------------------------------------------
// Prep: Qinv = (tril(L) tril(L)^T + 1e-4 I)^{-1}, once, in double.
// ---------------------------------------------------------------------------
__global__ void qinv_kernel(const float* __restrict__ L) {
    if (threadIdx.x != 0 || blockIdx.x != 0) return;
    double Lt[4][4];
    for (int i = 0; i < 4; i++)
        for (int j = 0; j < 4; j++)
            Lt[i][j] = (j <= i) ? (double)L[i * 4 + j] : 0.0;
    double M[4][8];
    for (int i = 0; i < 4; i++) {
        for (int j = 0; j < 4; j++) {
            double s = (i == j) ? 1e-4 : 0.0;
            for (int k = 0; k < 4; k++) s += Lt[i][k] * Lt[j][k];
            M[i][j] = s;
            M[i][4 + j] = (i == j) ? 1.0 : 0.0;
        }
    }
    for (int c = 0; c < 4; c++) {
        int p = c;
        for (int r = c + 1; r < 4; r++) if (fabs(M[r][c]) > fabs(M[p][c])) p = r;
        if (p != c) for (int j = 0; j < 8; j++) { double t = M[c][j]; M[c][j] = M[p][j]; M[p][j] = t; }
        double inv = 1.0 / M[c][c];
        for (int j = 0; j < 8; j++) M[c][j] *= inv;
        for (int r = 0; r < 4; r++) if (r != c) {
            double f = M[r][c];
            for (int j = 0; j < 8; j++) M[r][j] -= f * M[c][j];
        }
    }
    for (int i = 0; i < 4; i++)
        for (int j = 0; j < 4; j++)
            g_Qinv[i * 4 + j] = (float)M[i][4 + j];
}

// ===========================================================================
// Shared per-row MLP core: layer1 (k=17) -> h1(half2) -> layer2 accumulators.
// Used by both kernels via macros kept inline for register locality.
// ===========================================================================

// ---------------------------------------------------------------------------
// ACTOR kernel: mean -> QP -> u_out, log_prob, entropy.
// ---------------------------------------------------------------------------
__global__ __launch_bounds__(TPB, 3) void actor_kernel(
    const float* __restrict__ x, const float* __restrict__ sdfs,
    const float* __restrict__ grads, const float* __restrict__ f_x,
    const float* __restrict__ g_x, const float* __restrict__ action,
    const float* __restrict__ aW1, const float* __restrict__ ab1,
    const float* __restrict__ aW2, const float* __restrict__ ab2,
    const float* __restrict__ aW3, const float* __restrict__ ab3,
    const float* __restrict__ logstd, const float* __restrict__ s0,
    float* __restrict__ out, int N)
{
    __shared__ __align__(16) float sW1[OBS * HID];
    __shared__ __align__(16) float sW2[HID * HID];
    __shared__ __align__(16) float sW3[HID * ACT];
    __shared__ __align__(16) float sB1[HID], sB2[HID];
    __shared__ __align__(16) float sB3[ACT], sLogstd[ACT], sInvStd[ACT];
    __shared__ __align__(16) float sQinv[16];
    __shared__ __align__(16) float sMisc[4]; // 0: s0, 1: entropy

    const int tid = threadIdx.x;
    for (int i = tid; i < OBS * HID; i += TPB) sW1[i] = aW1[i];
    for (int i = tid; i < HID * HID; i += TPB) sW2[i] = aW2[i];
    for (int i = tid; i < HID * ACT; i += TPB) sW3[i] = aW3[i];
    if (tid < HID) { sB1[tid] = ab1[tid]; sB2[tid] = ab2[tid]; }
    if (tid < ACT) {
        float ls = logstd[tid];
        sB3[tid] = ab3[tid]; sLogstd[tid] = ls; sInvStd[tid] = expf(-ls);
    }
    if (tid < 16) sQinv[tid] = g_Qinv[tid];
    if (tid == 0) {
        sMisc[0] = s0[0];
        float e = 0.0f;
        for (int a = 0; a < ACT; a++) e += 0.5f + 0.5f * LOG_2PI + logstd[a];
        sMisc[1] = e;
    }
    __syncthreads();

    const int r0 = blockIdx.x * (2 * TPB) + tid;
    const int r1 = r0 + TPB;
    const bool ok0 = r0 < N, ok1 = r1 < N;
    const int rl0 = ok0 ? r0 : 0;
    const int rl1 = ok1 ? r1 : 0;

    __half2 h1A[32], h1B[32];

    // ---- layer 1 ----
    {
        float xA[OBS], xB[OBS];
#pragma unroll
        for (int i = 0; i < OBS; i++) { xA[i] = x[rl0 * OBS + i]; xB[i] = x[rl1 * OBS + i]; }
#pragma unroll 1
        for (int c1 = 0; c1 < 2; c1++) {
            ull hA[16], hB[16];
            const ulonglong2* bp = (const ulonglong2*)&sB1[c1 * 32];
#pragma unroll
            for (int q = 0; q < 8; q++) {
                ulonglong2 bb = bp[q];
                hA[2*q] = bb.x; hA[2*q+1] = bb.y;
                hB[2*q] = bb.x; hB[2*q+1] = bb.y;
            }
#pragma unroll 1
            for (int i = 0; i < OBS; i++) {
                const ull vA = dup2(xA[i]), vB = dup2(xB[i]);
                const ulonglong2* wp = (const ulonglong2*)&sW1[i * HID + c1 * 32];
#pragma unroll
                for (int q = 0; q < 8; q++) {
                    ulonglong2 ww = wp[q];
                    hA[2*q]   = fma2(ww.x, vA, hA[2*q]);
                    hA[2*q+1] = fma2(ww.y, vA, hA[2*q+1]);
                    hB[2*q]   = fma2(ww.x, vB, hB[2*q]);
                    hB[2*q+1] = fma2(ww.y, vB, hB[2*q+1]);
                }
            }
#pragma unroll
            for (int p = 0; p < 16; p++) {
                float2 t = upk(hA[p]);
                h1A[c1 * 16 + p] = __floats2half2_rn(tanh_fast(t.x), tanh_fast(t.y));
                t = upk(hB[p]);
                h1B[c1 * 16 + p] = __floats2half2_rn(tanh_fast(t.x), tanh_fast(t.y));
            }
        }
    }

    // ---- layer 2 + fused layer 3 ----
    ull mA01 = pk2(sB3[0], sB3[1]), mA23 = pk2(sB3[2], sB3[3]);
    ull mB01 = mA01, mB23 = mA23;
#pragma unroll 1
    for (int c = 0; c < 4; c++) {
        ull aA[8], aB[8];
        const ulonglong2* bp = (const ulonglong2*)&sB2[c * 16];
#pragma unroll
        for (int q = 0; q < 4; q++) {
            ulonglong2 bb = bp[q];
            aA[2*q] = bb.x; aA[2*q+1] = bb.y;
            aB[2*q] = bb.x; aB[2*q+1] = bb.y;
        }
#pragma unroll 4
        for (int ii = 0; ii < 32; ii++) {
            const float2 fA = __half22float2(h1A[ii]);
            const float2 fB = __half22float2(h1B[ii]);
            const ull a0 = dup2(fA.x), a1 = dup2(fA.y);
            const ull b0 = dup2(fB.x), b1 = dup2(fB.y);
            const ulonglong2* wp0 = (const ulonglong2*)&sW2[(2*ii) * HID + c * 16];
            const ulonglong2* wp1 = (const ulonglong2*)&sW2[(2*ii + 1) * HID + c * 16];
#pragma unroll
            for (int q = 0; q < 4; q++) {
                ulonglong2 w0 = wp0[q];
                aA[2*q]   = fma2(w0.x, a0, aA[2*q]);
                aA[2*q+1] = fma2(w0.y, a0, aA[2*q+1]);
                aB[2*q]   = fma2(w0.x, b0, aB[2*q]);
                aB[2*q+1] = fma2(w0.y, b0, aB[2*q+1]);
            }
#pragma unroll
            for (int q = 0; q < 4; q++) {
                ulonglong2 w1 = wp1[q];
                aA[2*q]   = fma2(w1.x, a1, aA[2*q]);
                aA[2*q+1] = fma2(w1.y, a1, aA[2*q+1]);
                aB[2*q]   = fma2(w1.x, b1, aB[2*q]);
                aB[2*q+1] = fma2(w1.y, b1, aB[2*q+1]);
            }
        }
#pragma unroll
        for (int p = 0; p < 8; p++) {
            const int j = c * 16 + 2 * p;
            float2 tA = upk(aA[p]);
            tA.x = tanh_fast(tA.x); tA.y = tanh_fast(tA.y);
            float2 tB = upk(aB[p]);
            tB.x = tanh_fast(tB.x); tB.y = tanh_fast(tB.y);
            const ulonglong2 w0 = *(const ulonglong2*)&sW3[j * ACT];
            const ulonglong2 w1 = *(const ulonglong2*)&sW3[(j + 1) * ACT];
            ull d;
            d = dup2(tA.x); mA01 = fma2(w0.x, d, mA01); mA23 = fma2(w0.y, d, mA23);
            d = dup2(tA.y); mA01 = fma2(w1.x, d, mA01); mA23 = fma2(w1.y, d, mA23);
            d = dup2(tB.x); mB01 = fma2(w0.x, d, mB01); mB23 = fma2(w0.y, d, mB23);
            d = dup2(tB.y); mB01 = fma2(w1.x, d, mB01); mB23 = fma2(w1.y, d, mB23);
        }
    }

    // ---- QP + outputs for both rows ----
#pragma unroll 1
    for (int rr = 0; rr < 2; rr++) {
        const int row = rr ? r1 : r0;
        const bool ok = rr ? ok1 : ok0;
        const int rl = ok ? row : 0;
        float m0, m1, m2, m3;
        {
            const float2 a = upk(rr ? mB01 : mA01);
            const float2 b = upk(rr ? mB23 : mA23);
            m0 = a.x; m1 = a.y; m2 = b.x; m3 = b.y;
        }
        float G0 = 0.f, G1 = 0.f, G2 = 0.f, G3 = 0.f, gf = 0.f;
#pragma unroll
        for (int s = 0; s < OBS; s++) {
            const float gr = grads[rl * OBS + s];
            const float4 gx = *(const float4*)&g_x[rl * OBS * ACT + s * ACT];
            G0 -= gr * gx.x; G1 -= gr * gx.y; G2 -= gr * gx.z; G3 -= gr * gx.w;
            gf += gr * f_x[rl * OBS + s];
        }
        const float4 av = *(const float4*)&action[rl * ACT];
        const float h = sMisc[0] + sdfs[rl] + gf
                      - (G0 * av.x + G1 * av.y + G2 * av.z + G3 * av.w);
        const float v0 = sQinv[0]  * G0 + sQinv[1]  * G1 + sQinv[2]  * G2 + sQinv[3]  * G3;
        const float v1 = sQinv[4]  * G0 + sQinv[5]  * G1 + sQinv[6]  * G2 + sQinv[7]  * G3;
        const float v2 = sQinv[8]  * G0 + sQinv[9]  * G1 + sQinv[10] * G2 + sQinv[11] * G3;
        const float v3 = sQinv[12] * G0 + sQinv[13] * G1 + sQinv[14] * G2 + sQinv[15] * G3;
        const float denom = G0 * v0 + G1 * v1 + G2 * v2 + G3 * v3;
        const float lam = fmaxf(0.0f, -h / denom);
        const float z0 = (av.x - m0) * sInvStd[0];
        const float z1 = (av.y - m1) * sInvStd[1];
        const float z2 = (av.z - m2) * sInvStd[2];
        const float z3 = (av.w - m3) * sInvStd[3];
        const float lp = -0.5f * (z0*z0 + z1*z1 + z2*z2 + z3*z3)
                       - (sLogstd[0] + sLogstd[1] + sLogstd[2] + sLogstd[3])
                       - 2.0f * LOG_2PI;
        if (ok) {
            *(float4*)&out[row * 4] = make_float4(m0 - lam * v0, m1 - lam * v1,
                                                  m2 - lam * v2, m3 - lam * v3);
            out[4 * N + row] = lp;
            out[5 * N + row] = sMisc[1];
        }
    }
}

// ---------------------------------------------------------------------------
// CRITIC kernel: value -> out[6N + row].
// ---------------------------------------------------------------------------
__global__ __launch_bounds__(TPB, 3) void critic_kernel(
    const float* __restrict__ x,
    const float* __restrict__ cW1, const float* __restrict__ cb1,
    const float* __restrict__ cW2, const float* __restrict__ cb2,
    const float* __restrict__ cW3, const float* __restrict__ cb3,
    float* __restrict__ out, int N)
{
    __shared__ __align__(16) float sW1[OBS * HID];
    __shared__ __align__(16) float sW2[HID * HID];
    __shared__ __align__(16) float sW3[HID];
    __shared__ __align__(16) float sB1[HID], sB2[HID];
    __shared__ float sC3;

    const int tid = threadIdx.x;
    for (int i = tid; i < OBS * HID; i += TPB) sW1[i] = cW1[i];
    for (int i = tid; i < HID * HID; i += TPB) sW2[i] = cW2[i];
    if (tid < HID) { sW3[tid] = cW3[tid]; sB1[tid] = cb1[tid]; sB2[tid] = cb2[tid]; }
    if (tid == 0) sC3 = cb3[0];
    __syncthreads();

    const int r0 = blockIdx.x * (2 * TPB) + tid;
    const int r1 = r0 + TPB;
    const bool ok0 = r0 < N, ok1 = r1 < N;
    const int rl0 = ok0 ? r0 : 0;
    const int rl1 = ok1 ? r1 : 0;

    __half2 h1A[32], h1B[32];

    // ---- layer 1 ----
    {
        float xA[OBS], xB[OBS];
#pragma unroll
        for (int i = 0; i < OBS; i++) { xA[i] = x[rl0 * OBS + i]; xB[i] = x[rl1 * OBS + i]; }
#pragma unroll 1
        for (int c1 = 0; c1 < 2; c1++) {
            ull hA[16], hB[16];
            const ulonglong2* bp = (const ulonglong2*)&sB1[c1 * 32];
#pragma unroll
            for (int q = 0; q < 8; q++) {
                ulonglong2 bb = bp[q];
                hA[2*q] = bb.x; hA[2*q+1] = bb.y;
                hB[2*q] = bb.x; hB[2*q+1] = bb.y;
            }
#pragma unroll 1
            for (int i = 0; i < OBS; i++) {
                const ull vA = dup2(xA[i]), vB = dup2(xB[i]);
                const ulonglong2* wp = (const ulonglong2*)&sW1[i * HID + c1 * 32];
#pragma unroll
                for (int q = 0; q < 8; q++) {
                    ulonglong2 ww = wp[q];
                    hA[2*q]   = fma2(ww.x, vA, hA[2*q]);
                    hA[2*q+1] = fma2(ww.y, vA, hA[2*q+1]);
                    hB[2*q]   = fma2(ww.x, vB, hB[2*q]);
                    hB[2*q+1] = fma2(ww.y, vB, hB[2*q+1]);
                }
            }
#pragma unroll
            for (int p = 0; p < 16; p++) {
                float2 t = upk(hA[p]);
                h1A[c1 * 16 + p] = __floats2half2_rn(tanh_fast(t.x), tanh_fast(t.y));
                t = upk(hB[p]);
                h1B[c1 * 16 + p] = __floats2half2_rn(tanh_fast(t.x), tanh_fast(t.y));
            }
        }
    }

    // ---- layer 2 + fused layer 3 ----
    ull vpA = pk2(sC3, 0.0f), vpB = vpA;
#pragma unroll 1
    for (int c = 0; c < 4; c++) {
        ull aA[8], aB[8];
        const ulonglong2* bp = (const ulonglong2*)&sB2[c * 16];
#pragma unroll
        for (int q = 0; q < 4; q++) {
            ulonglong2 bb = bp[q];
            aA[2*q] = bb.x; aA[2*q+1] = bb.y;
            aB[2*q] = bb.x; aB[2*q+1] = bb.y;
        }
#pragma unroll 4
        for (int ii = 0; ii < 32; ii++) {
            const float2 fA = __half22float2(h1A[ii]);
            const float2 fB = __half22float2(h1B[ii]);
            const ull a0 = dup2(fA.x), a1 = dup2(fA.y);
            const ull b0 = dup2(fB.x), b1 = dup2(fB.y);
            const ulonglong2* wp0 = (const ulonglong2*)&sW2[(2*ii) * HID + c * 16];
            const ulonglong2* wp1 = (const ulonglong2*)&sW2[(2*ii + 1) * HID + c * 16];
#pragma unroll
            for (int q = 0; q < 4; q++) {
                ulonglong2 w0 = wp0[q];
                aA[2*q]   = fma2(w0.x, a0, aA[2*q]);
                aA[2*q+1] = fma2(w0.y, a0, aA[2*q+1]);
                aB[2*q]   = fma2(w0.x, b0, aB[2*q]);
                aB[2*q+1] = fma2(w0.y, b0, aB[2*q+1]);
            }
#pragma unroll
            for (int q = 0; q < 4; q++) {
                ulonglong2 w1 = wp1[q];
                aA[2*q]   = fma2(w1.x, a1, aA[2*q]);
                aA[2*q+1] = fma2(w1.y, a1, aA[2*q+1]);
                aB[2*q]   = fma2(w1.x, b1, aB[2*q]);
                aB[2*q+1] = fma2(w1.y, b1, aB[2*q+1]);
            }
        }
#pragma unroll
        for (int p = 0; p < 8; p++) {
            const int j = c * 16 + 2 * p;
            float2 tA = upk(aA[p]);
            float2 tB = upk(aB[p]);
            const ull wv = *(const ull*)&sW3[j];
            vpA = fma2(wv, pk2(tanh_fast(tA.x), tanh_fast(tA.y)), vpA);
            vpB = fma2(wv, pk2(tanh_fast(tB.x), tanh_fast(tB.y)), vpB);
        }
    }
    {
        const float2 a = upk(vpA);
        const float2 b = upk(vpB);
        if (ok0) out[6 * N + r0] = a.x + a.y;
        if (ok1) out[6 * N + r1] = b.x + b.y;
    }
}

extern "C" void kernel_launch(void* const* d_in, const int* in_sizes, int n_in,
                              void* d_out, int out_size) {
    const float* x      = (const float*)d_in[0];
    const float* sdfs   = (const float*)d_in[1];
    const float* grads  = (const float*)d_in[2];
    const float* f_x    = (const float*)d_in[3];
    const float* g_x    = (const float*)d_in[4];
    const float* action = (const float*)d_in[5];
    const float* cW1 = (const float*)d_in[6];
    const float* cb1 = (const float*)d_in[7];
    const float* cW2 = (const float*)d_in[8];
    const float* cb2 = (const float*)d_in[9];
    const float* cW3 = (const float*)d_in[10];
    const float* cb3 = (const float*)d_in[11];
    const float* aW1 = (const float*)d_in[12];
    const float* ab1 = (const float*)d_in[13];
    const float* aW2 = (const float*)d_in[14];
    const float* ab2 = (const float*)d_in[15];
    const float* aW3 = (const float*)d_in[16];
    const float* ab3 = (const float*)d_in[17];
    const float* logstd = (const float*)d_in[18];
    const float* L      = (const float*)d_in[19];
    const float* s0     = (const float*)d_in[20];

    const int N = in_sizes[0] / OBS;
    float* out = (float*)d_out;

    qinv_kernel<<<1, 32>>>(L);
    const int rowsPerBlock = 2 * TPB;
    const int blocks = (N + rowsPerBlock - 1) / rowsPerBlock;
    actor_kernel<<<blocks, TPB>>>(x, sdfs, grads, f_x, g_x, action,
                                  aW1, ab1, aW2, ab2, aW3, ab3,
                                  logstd, s0, out, N);
    critic_kernel<<<blocks, TPB>>>(x, cW1, cb1, cW2, cb2, cW3, cb3, out, N);
}

// round 13
// speedup vs baseline: 1.7583x; 1.0751x over previous
#include <cuda_runtime.h>
#include <cuda_fp16.h>
#include <math.h>

#define OBS 17
#define ACT 4
#define HID 64
#define LOG_2PI 1.8378770664093453f
#define TPB 128
typedef unsigned long long ull;

// ---- shared buffer layout (float offsets), one union for both branches ----
#define F_W1   0       // 17*64 = 1088
#define F_W2   1088    // 64*64 = 4096
#define F_W3   5184    // actor: 64*4 = 256 ; critic: 64
#define F_B1   5440    // 64
#define F_B2   5504    // 64
#define F_B3   5568    // 4 (actor bias3)
#define F_LOG  5572    // 4
#define F_INV  5576    // 4
#define F_QINV 5584    // 16
#define F_MISC 5600    // 0: s0|cb3, 1: entropy
#define SM_FLOATS 5604

__device__ __forceinline__ float tanh_fast(float v) {
    float r; asm("tanh.approx.f32 %0, %1;" : "=f"(r) : "f"(v)); return r;
}
__device__ __forceinline__ ull fma2(ull a, ull b, ull c) {
    ull d; asm("fma.rn.f32x2 %0, %1, %2, %3;" : "=l"(d) : "l"(a), "l"(b), "l"(c)); return d;
}
__device__ __forceinline__ ull dup2(float v) {
    ull d; asm("mov.b64 %0, {%1, %1};" : "=l"(d) : "f"(v)); return d;
}
__device__ __forceinline__ ull pk2(float x, float y) {
    ull d; asm("mov.b64 %0, {%1, %2};" : "=l"(d) : "f"(x), "f"(y)); return d;
}
__device__ __forceinline__ float2 upk(ull p) {
    float2 r; asm("mov.b64 {%0, %1}, %2;" : "=f"(r.x), "=f"(r.y) : "l"(p)); return r;
}

// fp32 4x4 SPD inverse: Gauss-Jordan w/ pivoting + 2 Newton refinements.
__device__ void qinv_f32(const float* __restrict__ L, float* __restrict__ outQinv) {
    float Q[16], M[4][8];
    // Q = tril(L) tril(L)^T + 1e-4 I
#pragma unroll
    for (int i = 0; i < 4; i++)
#pragma unroll
        for (int j = 0; j < 4; j++) {
            float s = (i == j) ? 1e-4f : 0.0f;
#pragma unroll
            for (int k = 0; k < 4; k++)
                if (k <= i && k <= j) s += L[i * 4 + k] * L[j * 4 + k];
            Q[i * 4 + j] = s;
        }
#pragma unroll
    for (int i = 0; i < 4; i++)
#pragma unroll
        for (int j = 0; j < 4; j++) {
            M[i][j] = Q[i * 4 + j];
            M[i][4 + j] = (i == j) ? 1.0f : 0.0f;
        }
    for (int c = 0; c < 4; c++) {
        int p = c;
        for (int r = c + 1; r < 4; r++) if (fabsf(M[r][c]) > fabsf(M[p][c])) p = r;
        if (p != c)
            for (int j = 0; j < 8; j++) { float t = M[c][j]; M[c][j] = M[p][j]; M[p][j] = t; }
        const float inv = 1.0f / M[c][c];
        for (int j = 0; j < 8; j++) M[c][j] *= inv;
        for (int r = 0; r < 4; r++) if (r != c) {
            const float f = M[r][c];
            for (int j = 0; j < 8; j++) M[r][j] -= f * M[c][j];
        }
    }
    float X[16];
#pragma unroll
    for (int i = 0; i < 4; i++)
#pragma unroll
        for (int j = 0; j < 4; j++) X[i * 4 + j] = M[i][4 + j];
    // Newton: X <- X (2I - Q X), twice
#pragma unroll 1
    for (int it = 0; it < 2; it++) {
        float R[16];
#pragma unroll
        for (int i = 0; i < 4; i++)
#pragma unroll
            for (int j = 0; j < 4; j++) {
                float s = (i == j) ? 2.0f : 0.0f;
#pragma unroll
                for (int k = 0; k < 4; k++) s -= Q[i * 4 + k] * X[k * 4 + j];
                R[i * 4 + j] = s;
            }
        float Xn[16];
#pragma unroll
        for (int i = 0; i < 4; i++)
#pragma unroll
            for (int j = 0; j < 4; j++) {
                float s = 0.0f;
#pragma unroll
                for (int k = 0; k < 4; k++) s += X[i * 4 + k] * R[k * 4 + j];
                Xn[i * 4 + j] = s;
            }
#pragma unroll
        for (int i = 0; i < 16; i++) X[i] = Xn[i];
    }
#pragma unroll
    for (int i = 0; i < 16; i++) outQinv[i] = X[i];
}

// ---------------------------------------------------------------------------
// Fat-grid kernel: blocks [0, half) = actor, [half, 2*half) = critic.
// 2 rows/thread, packed f32x2 math, fp16 h1.
// ---------------------------------------------------------------------------
__global__ __launch_bounds__(TPB, 3) void fused_kernel(
    const float* __restrict__ x, const float* __restrict__ sdfs,
    const float* __restrict__ grads, const float* __restrict__ f_x,
    const float* __restrict__ g_x, const float* __restrict__ action,
    const float* __restrict__ cW1, const float* __restrict__ cb1,
    const float* __restrict__ cW2, const float* __restrict__ cb2,
    const float* __restrict__ cW3, const float* __restrict__ cb3,
    const float* __restrict__ aW1, const float* __restrict__ ab1,
    const float* __restrict__ aW2, const float* __restrict__ ab2,
    const float* __restrict__ aW3, const float* __restrict__ ab3,
    const float* __restrict__ logstd, const float* __restrict__ L,
    const float* __restrict__ s0,
    float* __restrict__ out, int N, int halfBlocks)
{
    __shared__ __align__(16) float sm[SM_FLOATS];
    const int tid = threadIdx.x;
    const bool isActor = (int)blockIdx.x < halfBlocks;
    const int blk = isActor ? (int)blockIdx.x : (int)blockIdx.x - halfBlocks;

    // ================= staging =================
    if (isActor) {
        for (int i = tid; i < OBS * HID; i += TPB) sm[F_W1 + i] = aW1[i];
        for (int i = tid; i < HID * HID; i += TPB) sm[F_W2 + i] = aW2[i];
        for (int i = tid; i < HID * ACT; i += TPB) sm[F_W3 + i] = aW3[i];
        if (tid >= 64 && tid < 128) { sm[F_B1 + tid - 64] = ab1[tid - 64]; sm[F_B2 + tid - 64] = ab2[tid - 64]; }
        if (tid >= 32 && tid < 36) {
            const int a = tid - 32;
            const float ls = logstd[a];
            sm[F_B3 + a] = ab3[a]; sm[F_LOG + a] = ls; sm[F_INV + a] = expf(-ls);
        }
        if (tid == 1) {
            sm[F_MISC + 0] = s0[0];
            float e = 0.0f;
            for (int a = 0; a < ACT; a++) e += 0.5f + 0.5f * LOG_2PI + logstd[a];
            sm[F_MISC + 1] = e;
        }
        if (tid == 0) qinv_f32(L, &sm[F_QINV]);
    } else {
        for (int i = tid; i < OBS * HID; i += TPB) sm[F_W1 + i] = cW1[i];
        for (int i = tid; i < HID * HID; i += TPB) sm[F_W2 + i] = cW2[i];
        if (tid < 64) {
            sm[F_W3 + tid] = cW3[tid];
            sm[F_B1 + tid] = cb1[tid];
            sm[F_B2 + tid] = cb2[tid];
        }
        if (tid == 0) sm[F_MISC + 0] = cb3[0];
    }
    __syncthreads();

    const int r0 = blk * (2 * TPB) + tid;
    const int r1 = r0 + TPB;
    const bool ok0 = r0 < N, ok1 = r1 < N;
    const int rl0 = ok0 ? r0 : 0;
    const int rl1 = ok1 ? r1 : 0;

    __half2 h1A[32], h1B[32];

    // ================= layer 1 (both branches identical) =================
    {
        float xA[OBS], xB[OBS];
#pragma unroll
        for (int i = 0; i < OBS; i++) { xA[i] = x[rl0 * OBS + i]; xB[i] = x[rl1 * OBS + i]; }
#pragma unroll 1
        for (int c1 = 0; c1 < 2; c1++) {
            ull hA[16], hB[16];
            const ulonglong2* bp = (const ulonglong2*)&sm[F_B1 + c1 * 32];
#pragma unroll
            for (int q = 0; q < 8; q++) {
                ulonglong2 bb = bp[q];
                hA[2*q] = bb.x; hA[2*q+1] = bb.y;
                hB[2*q] = bb.x; hB[2*q+1] = bb.y;
            }
#pragma unroll 1
            for (int i = 0; i < OBS; i++) {
                const ull vA = dup2(xA[i]), vB = dup2(xB[i]);
                const ulonglong2* wp = (const ulonglong2*)&sm[F_W1 + i * HID + c1 * 32];
#pragma unroll
                for (int q = 0; q < 8; q++) {
                    ulonglong2 ww = wp[q];
                    hA[2*q]   = fma2(ww.x, vA, hA[2*q]);
                    hA[2*q+1] = fma2(ww.y, vA, hA[2*q+1]);
                    hB[2*q]   = fma2(ww.x, vB, hB[2*q]);
                    hB[2*q+1] = fma2(ww.y, vB, hB[2*q+1]);
                }
            }
#pragma unroll
            for (int p = 0; p < 16; p++) {
                float2 t = upk(hA[p]);
                h1A[c1 * 16 + p] = __floats2half2_rn(tanh_fast(t.x), tanh_fast(t.y));
                t = upk(hB[p]);
                h1B[c1 * 16 + p] = __floats2half2_rn(tanh_fast(t.x), tanh_fast(t.y));
            }
        }
    }

    // ================= layer 2 + fused layer 3 =================
    ull mA01, mA23, mB01, mB23;   // actor: mean pairs ; critic: value in mA01/mB01
    if (isActor) {
        mA01 = pk2(sm[F_B3 + 0], sm[F_B3 + 1]);
        mA23 = pk2(sm[F_B3 + 2], sm[F_B3 + 3]);
        mB01 = mA01; mB23 = mA23;
    } else {
        mA01 = pk2(sm[F_MISC + 0], 0.0f);
        mB01 = mA01; mA23 = 0ull; mB23 = 0ull;
    }
#pragma unroll 1
    for (int c = 0; c < 4; c++) {
        ull aA[8], aB[8];
        const ulonglong2* bp = (const ulonglong2*)&sm[F_B2 + c * 16];
#pragma unroll
        for (int q = 0; q < 4; q++) {
            ulonglong2 bb = bp[q];
            aA[2*q] = bb.x; aA[2*q+1] = bb.y;
            aB[2*q] = bb.x; aB[2*q+1] = bb.y;
        }
#pragma unroll 4
        for (int ii = 0; ii < 32; ii++) {
            const float2 fA = __half22float2(h1A[ii]);
            const float2 fB = __half22float2(h1B[ii]);
            const ull a0 = dup2(fA.x), a1 = dup2(fA.y);
            const ull b0 = dup2(fB.x), b1 = dup2(fB.y);
            const ulonglong2* wp0 = (const ulonglong2*)&sm[F_W2 + (2*ii) * HID + c * 16];
            const ulonglong2* wp1 = (const ulonglong2*)&sm[F_W2 + (2*ii + 1) * HID + c * 16];
#pragma unroll
            for (int q = 0; q < 4; q++) {
                ulonglong2 w0 = wp0[q];
                aA[2*q]   = fma2(w0.x, a0, aA[2*q]);
                aA[2*q+1] = fma2(w0.y, a0, aA[2*q+1]);
                aB[2*q]   = fma2(w0.x, b0, aB[2*q]);
                aB[2*q+1] = fma2(w0.y, b0, aB[2*q+1]);
            }
#pragma unroll
            for (int q = 0; q < 4; q++) {
                ulonglong2 w1 = wp1[q];
                aA[2*q]   = fma2(w1.x, a1, aA[2*q]);
                aA[2*q+1] = fma2(w1.y, a1, aA[2*q+1]);
                aB[2*q]   = fma2(w1.x, b1, aB[2*q]);
                aB[2*q+1] = fma2(w1.y, b1, aB[2*q+1]);
            }
        }
#pragma unroll
        for (int p = 0; p < 8; p++) {
            const int j = c * 16 + 2 * p;
            float2 tA = upk(aA[p]);
            tA.x = tanh_fast(tA.x); tA.y = tanh_fast(tA.y);
            float2 tB = upk(aB[p]);
            tB.x = tanh_fast(tB.x); tB.y = tanh_fast(tB.y);
            if (isActor) {
                const ulonglong2 w0 = *(const ulonglong2*)&sm[F_W3 + j * ACT];
                const ulonglong2 w1 = *(const ulonglong2*)&sm[F_W3 + (j + 1) * ACT];
                ull d;
                d = dup2(tA.x); mA01 = fma2(w0.x, d, mA01); mA23 = fma2(w0.y, d, mA23);
                d = dup2(tA.y); mA01 = fma2(w1.x, d, mA01); mA23 = fma2(w1.y, d, mA23);
                d = dup2(tB.x); mB01 = fma2(w0.x, d, mB01); mB23 = fma2(w0.y, d, mB23);
                d = dup2(tB.y); mB01 = fma2(w1.x, d, mB01); mB23 = fma2(w1.y, d, mB23);
            } else {
                const ull wv = *(const ull*)&sm[F_W3 + j];
                mA01 = fma2(wv, pk2(tA.x, tA.y), mA01);
                mB01 = fma2(wv, pk2(tB.x, tB.y), mB01);
            }
        }
    }

    // ================= outputs =================
    if (!isActor) {
        const float2 a = upk(mA01);
        const float2 b = upk(mB01);
        if (ok0) out[6 * N + r0] = a.x + a.y;
        if (ok1) out[6 * N + r1] = b.x + b.y;
        return;
    }

    // actor: QP + log_prob + entropy for both rows
#pragma unroll 1
    for (int rr = 0; rr < 2; rr++) {
        const int row = rr ? r1 : r0;
        const bool ok = rr ? ok1 : ok0;
        const int rl = ok ? row : 0;
        float m0, m1, m2, m3;
        {
            const float2 a = upk(rr ? mB01 : mA01);
            const float2 b = upk(rr ? mB23 : mA23);
            m0 = a.x; m1 = a.y; m2 = b.x; m3 = b.y;
        }
        float G0 = 0.f, G1 = 0.f, G2 = 0.f, G3 = 0.f, gf = 0.f;
#pragma unroll
        for (int s = 0; s < OBS; s++) {
            const float gr = grads[rl * OBS + s];
            const float4 gx = *(const float4*)&g_x[rl * OBS * ACT + s * ACT];
            G0 -= gr * gx.x; G1 -= gr * gx.y; G2 -= gr * gx.z; G3 -= gr * gx.w;
            gf += gr * f_x[rl * OBS + s];
        }
        const float4 av = *(const float4*)&action[rl * ACT];
        const float h = sm[F_MISC + 0] + sdfs[rl] + gf
                      - (G0 * av.x + G1 * av.y + G2 * av.z + G3 * av.w);
        const float* q = &sm[F_QINV];
        const float v0 = q[0]  * G0 + q[1]  * G1 + q[2]  * G2 + q[3]  * G3;
        const float v1 = q[4]  * G0 + q[5]  * G1 + q[6]  * G2 + q[7]  * G3;
        const float v2 = q[8]  * G0 + q[9]  * G1 + q[10] * G2 + q[11] * G3;
        const float v3 = q[12] * G0 + q[13] * G1 + q[14] * G2 + q[15] * G3;
        const float denom = G0 * v0 + G1 * v1 + G2 * v2 + G3 * v3;
        const float lam = fmaxf(0.0f, -h / denom);
        const float z0 = (av.x - m0) * sm[F_INV + 0];
        const float z1 = (av.y - m1) * sm[F_INV + 1];
        const float z2 = (av.z - m2) * sm[F_INV + 2];
        const float z3 = (av.w - m3) * sm[F_INV + 3];
        const float lp = -0.5f * (z0*z0 + z1*z1 + z2*z2 + z3*z3)
                       - (sm[F_LOG + 0] + sm[F_LOG + 1] + sm[F_LOG + 2] + sm[F_LOG + 3])
                       - 2.0f * LOG_2PI;
        if (ok) {
            *(float4*)&out[row * 4] = make_float4(m0 - lam * v0, m1 - lam * v1,
                                                  m2 - lam * v2, m3 - lam * v3);
            out[4 * N + row] = lp;
            out[5 * N + row] = sm[F_MISC + 1];
        }
    }
}

extern "C" void kernel_launch(void* const* d_in, const int* in_sizes, int n_in,
                              void* d_out, int out_size) {
    const float* x      = (const float*)d_in[0];
    const float* sdfs   = (const float*)d_in[1];
    const float* grads  = (const float*)d_in[2];
    const float* f_x    = (const float*)d_in[3];
    const float* g_x    = (const float*)d_in[4];
    const float* action = (const float*)d_in[5];
    const float* cW1 = (const float*)d_in[6];
    const float* cb1 = (const float*)d_in[7];
    const float* cW2 = (const float*)d_in[8];
    const float* cb2 = (const float*)d_in[9];
    const float* cW3 = (const float*)d_in[10];
    const float* cb3 = (const float*)d_in[11];
    const float* aW1 = (const float*)d_in[12];
    const float* ab1 = (const float*)d_in[13];
    const float* aW2 = (const float*)d_in[14];
    const float* ab2 = (const float*)d_in[15];
    const float* aW3 = (const float*)d_in[16];
    const float* ab3 = (const float*)d_in[17];
    const float* logstd = (const float*)d_in[18];
    const float* L      = (const float*)d_in[19];
    const float* s0     = (const float*)d_in[20];

    const int N = in_sizes[0] / OBS;
    float* out = (float*)d_out;

    const int rowsPerBlock = 2 * TPB;
    const int halfBlocks = (N + rowsPerBlock - 1) / rowsPerBlock;
    fused_kernel<<<2 * halfBlocks, TPB>>>(x, sdfs, grads, f_x, g_x, action,
                                          cW1, cb1, cW2, cb2, cW3, cb3,
                                          aW1, ab1, aW2, ab2, aW3, ab3,
                                          logstd, L, s0, out, N, halfBlocks);
}